// round 10
// baseline (speedup 1.0000x reference)
#include <cuda_runtime.h>
#include <math.h>

#define H 256
#define MAXE 500000
#define MAXG 256
#define FRONTIER_BONUS 0.5f
#define LN_EPS 1e-5f
#define F32_EPS 1.1920929e-07f
#define LOG_EPS -15.942385152878742f   // ln(2^-23)
#define NBLK_P1 1184
#define PG 4                            // graphs per stop-head block

// ---------------- device scratch ----------------
// __align__(16) REQUIRED: float4 (LDG.128) access to w_att and S.
struct __align__(16) Scratch {
    float    S[MAXG * H];     // segment sums of edge_tokens
    float    w_att[H];        // att_vec @ W_edge  (atomic partials)
    float    w_q[H];          // att_vec @ W_query (atomic partials)
    unsigned maxenc[MAXG];    // order-preserving-uint segment max (0 == -inf)
};
__device__ Scratch g_z;
__device__ float g_qatt[MAXG];                      // overwritten each run
__device__ float g_att[MAXE];                       // overwritten each run
__device__ int   g_seg[MAXG + 1];                   // overwritten each run
__device__ __align__(16) float g_xn[MAXG * 2 * H];  // layernormed stop input
__device__ float g_WTe[H * H];                      // W_edge^T (overwritten)
__device__ float g_WT1[2 * H * H];                  // W1^T     (overwritten)

// order-preserving float <-> uint; memset-0 acts as -infinity identity
__device__ __forceinline__ unsigned fenc(float f) {
    unsigned u = (unsigned)__float_as_int(f);
    return (u & 0x80000000u) ? ~u : (u | 0x80000000u);
}
__device__ __forceinline__ float fdec(unsigned u) {
    unsigned v = (u & 0x80000000u) ? (u & 0x7FFFFFFFu) : ~u;
    return __int_as_float((int)v);
}

// ------- setup: prew partials (0-31) + seg (32-33) + transposes (34-225) ---
__global__ void __launch_bounds__(256) setup_k(const float* __restrict__ W_edge,
                       const float* __restrict__ W_query,
                       const float* __restrict__ W1,
                       const float* __restrict__ att_vec,
                       const int* __restrict__ batch, int E, int G) {
    __shared__ float sh[32][33];
    int b = blockIdx.x, t = threadIdx.x;
    if (b < 32) {
        int m = b >> 4;                   // 0: W_edge, 1: W_query
        int c = b & 15;                   // row chunk of 16
        const float* W = m ? W_query : W_edge;
        int i0 = c * 16;
        float s = 0.f;
        #pragma unroll
        for (int i = 0; i < 16; i++)
            s = fmaf(__ldg(att_vec + i0 + i), __ldg(W + (i0 + i) * H + t), s);
        atomicAdd((m ? g_z.w_q : g_z.w_att) + t, s);
    } else if (b < 34) {
        int i = (b - 32) * 256 + t;
        if (i > G) return;
        int lo = 0, hi = E;
        while (lo < hi) {
            int mid = (lo + hi) >> 1;
            if (__ldg(batch + mid) < i) lo = mid + 1; else hi = mid;
        }
        g_seg[i] = lo;
    } else if (b < 98) {
        // transpose W_edge [256 x 256] -> g_WTe: 8x8 tiles of 32x32
        int bt = b - 34;
        int ti = bt >> 3, tj = bt & 7;
        int x = t & 31, y = t >> 5;       // 32 x 8
        #pragma unroll
        for (int k = 0; k < 4; k++)
            sh[y + 8 * k][x] = __ldg(W_edge + (ti * 32 + y + 8 * k) * H + tj * 32 + x);
        __syncthreads();
        #pragma unroll
        for (int k = 0; k < 4; k++)
            g_WTe[(tj * 32 + y + 8 * k) * H + ti * 32 + x] = sh[x][y + 8 * k];
    } else {
        // transpose W1 [256 x 512] -> g_WT1 [512 x 256]: 8x16 tiles
        int bt = b - 98;
        int ti = bt >> 4, tj = bt & 15;
        int x = t & 31, y = t >> 5;
        #pragma unroll
        for (int k = 0; k < 4; k++)
            sh[y + 8 * k][x] = __ldg(W1 + (ti * 32 + y + 8 * k) * (2 * H) + tj * 32 + x);
        __syncthreads();
        #pragma unroll
        for (int k = 0; k < 4; k++)
            g_WT1[(tj * 32 + y + 8 * k) * H + ti * 32 + x] = sh[x][y + 8 * k];
    }
}

// ---------------- qatt[g] = question_tokens[g] . w_q ----------------
__global__ void __launch_bounds__(256) qatt_k(const float* __restrict__ qtok, int G) {
    int w = threadIdx.x >> 5, l = threadIdx.x & 31;
    int g = blockIdx.x * 8 + w;
    if (g >= G) return;
    float s = 0.f;
    #pragma unroll
    for (int k = 0; k < 8; k++) {
        int j = l + 32 * k;
        s = fmaf(qtok[(size_t)g * H + j], g_z.w_q[j], s);
    }
    #pragma unroll
    for (int sh = 16; sh; sh >>= 1) s += __shfl_xor_sync(0xFFFFFFFFu, s, sh);
    if (l == 0) g_qatt[g] = s;
}

// ---------------- main streaming pass: warp-per-edge, x4 unroll ----------
struct RunState {
    float4 a0, a1;
    float rmax, qcur;
    int cur;
};

__device__ __forceinline__ void flush_run(RunState& st, int l) {
    if (st.cur < 0) return;
    float* Sp = &g_z.S[st.cur * H];
    atomicAdd(Sp + 4 * l + 0, st.a0.x);
    atomicAdd(Sp + 4 * l + 1, st.a0.y);
    atomicAdd(Sp + 4 * l + 2, st.a0.z);
    atomicAdd(Sp + 4 * l + 3, st.a0.w);
    atomicAdd(Sp + 128 + 4 * l + 0, st.a1.x);
    atomicAdd(Sp + 128 + 4 * l + 1, st.a1.y);
    atomicAdd(Sp + 128 + 4 * l + 2, st.a1.z);
    atomicAdd(Sp + 128 + 4 * l + 3, st.a1.w);
    if (l == 0) atomicMax(&g_z.maxenc[st.cur], fenc(st.rmax));
}

__device__ __forceinline__ void process_edge(RunState& st, int g, int selv,
                                             float4 x0, float4 x1,
                                             float4 wa0, float4 wa1,
                                             int e, int l) {
    if (g != st.cur) {
        flush_run(st, l);
        st.a0 = make_float4(0.f, 0.f, 0.f, 0.f);
        st.a1 = make_float4(0.f, 0.f, 0.f, 0.f);
        st.rmax = -INFINITY; st.cur = g;
        st.qcur = g_qatt[g];
    }
    st.a0.x += x0.x; st.a0.y += x0.y; st.a0.z += x0.z; st.a0.w += x0.w;
    st.a1.x += x1.x; st.a1.y += x1.y; st.a1.z += x1.z; st.a1.w += x1.w;
    float d = x0.x * wa0.x + x0.y * wa0.y + x0.z * wa0.z + x0.w * wa0.w
            + x1.x * wa1.x + x1.y * wa1.y + x1.z * wa1.z + x1.w * wa1.w;
    #pragma unroll
    for (int sh = 16; sh; sh >>= 1) d += __shfl_xor_sync(0xFFFFFFFFu, d, sh);
    float r = d + st.qcur;
    r = r > 0.f ? r : 0.2f * r;                       // LeakyReLU(0.2)
    if (selv == 0) r += FRONTIER_BONUS;               // candidate == frontier
    if (l == 0) g_att[e] = r;
    st.rmax = fmaxf(st.rmax, r);
}

__global__ void __launch_bounds__(256) pass1_k(const float* __restrict__ x,
                        const int* __restrict__ batch,
                        const int* __restrict__ sel,
                        int E) {
    int chunk = (E + NBLK_P1 - 1) / NBLK_P1;
    int lo = blockIdx.x * chunk;
    int hi = min(E, lo + chunk);
    int w = threadIdx.x >> 5, l = threadIdx.x & 31;

    const float4* wav = (const float4*)g_z.w_att;
    float4 wa0 = wav[l];
    float4 wa1 = wav[32 + l];

    RunState st;
    st.a0 = make_float4(0.f, 0.f, 0.f, 0.f);
    st.a1 = make_float4(0.f, 0.f, 0.f, 0.f);
    st.cur = -1; st.rmax = -INFINITY; st.qcur = 0.f;

    int e = lo + w;
    // x4 unroll: all loads unconditional and front-batched (8 LDG.128 in flight)
    for (; e + 24 < hi; e += 32) {
        int e1 = e + 8, e2 = e + 16, e3 = e + 24;
        int g0 = __ldg(batch + e);
        int g1 = __ldg(batch + e1);
        int g2 = __ldg(batch + e2);
        int g3 = __ldg(batch + e3);
        int s0 = __ldg(sel + e);
        int s1 = __ldg(sel + e1);
        int s2 = __ldg(sel + e2);
        int s3 = __ldg(sel + e3);
        const float4* r0 = (const float4*)(x + (size_t)e  * H);
        const float4* r1 = (const float4*)(x + (size_t)e1 * H);
        const float4* r2 = (const float4*)(x + (size_t)e2 * H);
        const float4* r3 = (const float4*)(x + (size_t)e3 * H);
        float4 xa0 = __ldg(r0 + l), xa1 = __ldg(r0 + 32 + l);
        float4 xb0 = __ldg(r1 + l), xb1 = __ldg(r1 + 32 + l);
        float4 xc0 = __ldg(r2 + l), xc1 = __ldg(r2 + 32 + l);
        float4 xd0 = __ldg(r3 + l), xd1 = __ldg(r3 + 32 + l);
        process_edge(st, g0, s0, xa0, xa1, wa0, wa1, e,  l);
        process_edge(st, g1, s1, xb0, xb1, wa0, wa1, e1, l);
        process_edge(st, g2, s2, xc0, xc1, wa0, wa1, e2, l);
        process_edge(st, g3, s3, xd0, xd1, wa0, wa1, e3, l);
    }
    for (; e < hi; e += 8) {
        int g = __ldg(batch + e);
        int s = __ldg(sel + e);
        const float4* row = (const float4*)(x + (size_t)e * H);
        float4 x0 = __ldg(row + l);
        float4 x1 = __ldg(row + 32 + l);
        process_edge(st, g, s, x0, x1, wa0, wa1, e, l);
    }
    flush_run(st, l);
}

// ---------------- block reduction helper (PG values at once) --------------
__device__ __forceinline__ void block_sum4(float v[PG], float4* red4, float out[PG]) {
    int l = threadIdx.x & 31, w = threadIdx.x >> 5;
    #pragma unroll
    for (int sh = 16; sh; sh >>= 1) {
        #pragma unroll
        for (int gg = 0; gg < PG; gg++)
            v[gg] += __shfl_xor_sync(0xFFFFFFFFu, v[gg], sh);
    }
    if (l == 0) red4[w] = make_float4(v[0], v[1], v[2], v[3]);
    __syncthreads();
    if (w == 0) {
        float4 xv = (l < 8) ? red4[l] : make_float4(0.f, 0.f, 0.f, 0.f);
        #pragma unroll
        for (int sh = 4; sh; sh >>= 1) {
            xv.x += __shfl_xor_sync(0xFFFFFFFFu, xv.x, sh);
            xv.y += __shfl_xor_sync(0xFFFFFFFFu, xv.y, sh);
            xv.z += __shfl_xor_sync(0xFFFFFFFFu, xv.z, sh);
            xv.w += __shfl_xor_sync(0xFFFFFFFFu, xv.w, sh);
        }
        if (l == 0) red4[0] = xv;
    }
    __syncthreads();
    float4 r = red4[0];
    out[0] = r.x; out[1] = r.y; out[2] = r.z; out[3] = r.w;
    __syncthreads();
}

// ------- fused post: softmax (blocks [0,G)) + pooled matvec + LN ----------
__global__ void __launch_bounds__(256) post_k(
        const int* __restrict__ sel, const float* __restrict__ qtok,
        const float* __restrict__ ln_g, const float* __restrict__ ln_b,
        float* __restrict__ out_edge, float* __restrict__ out_pooled,
        int E, int G) {
    int t = threadIdx.x, l = t & 31, w = t >> 5;

    if (blockIdx.x < (unsigned)G) {
        // -------- segment softmax + edge logits --------
        __shared__ float red[32];
        __shared__ float s_lsum;
        int g = blockIdx.x;
        int lo = __ldg(g_seg + g);
        int hi = __ldg(g_seg + g + 1);
        if (lo >= hi) return;

        float m = fdec(g_z.maxenc[g]);
        float s = 0.f;
        for (int e = lo + t; e < hi; e += 256)
            if (__ldg(sel + e) == 0) s += __expf(__ldg(g_att + e) - m);
        #pragma unroll
        for (int sh = 16; sh; sh >>= 1) s += __shfl_xor_sync(0xFFFFFFFFu, s, sh);
        if (l == 0) red[w] = s;
        __syncthreads();
        if (w == 0) {
            float v = (l < 8) ? red[l] : 0.f;
            #pragma unroll
            for (int sh = 4; sh; sh >>= 1) v += __shfl_xor_sync(0xFFFFFFFFu, v, sh);
            if (l == 0) s_lsum = __logf(fmaxf(v, F32_EPS));
        }
        __syncthreads();
        float lsum = s_lsum;
        // log(max(p,eps)) = max(log p, log eps); log p = (att-m) - lsum
        for (int e = lo + t; e < hi; e += 256) {
            float o = LOG_EPS;
            if (__ldg(sel + e) == 0)
                o = fmaxf(__ldg(g_att + e) - m - lsum, LOG_EPS);
            out_edge[e] = o;
        }
    } else {
        // -------- pooled matvec (coalesced via W_edge^T) + LayerNorm ------
        __shared__ __align__(16) float ssh[PG][H];   // S/denom
        __shared__ float4 red4[32];
        int g0 = (blockIdx.x - G) * PG;

        #pragma unroll
        for (int gg = 0; gg < PG; gg++) {
            int g = g0 + gg;
            float v = 0.f;
            if (g < G) {
                int c = __ldg(g_seg + g + 1) - __ldg(g_seg + g);
                v = g_z.S[g * H + t] / fmaxf((float)c, 1.0f);
            }
            ssh[gg][t] = v;
        }
        __syncthreads();

        // thread t owns output row t: acc[gg] += ssh[gg][j] * WTe[j][t]
        // WTe load coalesced across threads; ssh is a broadcast; no shuffles.
        float acc[PG];
        #pragma unroll
        for (int gg = 0; gg < PG; gg++) acc[gg] = 0.f;
        #pragma unroll 8
        for (int j = 0; j < H; j++) {
            float wv = __ldg(g_WTe + j * H + t);
            #pragma unroll
            for (int gg = 0; gg < PG; gg++)
                acc[gg] = fmaf(ssh[gg][j], wv, acc[gg]);
        }

        float pe[PG], qv[PG];
        #pragma unroll
        for (int gg = 0; gg < PG; gg++) {
            int g = g0 + gg;
            pe[gg] = acc[gg];
            qv[gg] = (g < G) ? qtok[(size_t)g * H + t] : 0.f;
            if (g < G) out_pooled[(size_t)g * H + t] = pe[gg];
        }

        float v[PG], mu[PG], var[PG];
        #pragma unroll
        for (int gg = 0; gg < PG; gg++) v[gg] = pe[gg] + qv[gg];
        block_sum4(v, red4, mu);
        float d0[PG], d1[PG];
        #pragma unroll
        for (int gg = 0; gg < PG; gg++) {
            mu[gg] *= (1.0f / (2 * H));
            d0[gg] = pe[gg] - mu[gg];
            d1[gg] = qv[gg] - mu[gg];
            v[gg] = d0[gg] * d0[gg] + d1[gg] * d1[gg];
        }
        block_sum4(v, red4, var);
        float lg0 = ln_g[t], lb0 = ln_b[t], lg1 = ln_g[H + t], lb1 = ln_b[H + t];
        #pragma unroll
        for (int gg = 0; gg < PG; gg++) {
            int g = g0 + gg;
            if (g >= G) continue;
            float rstd = rsqrtf(var[gg] * (1.0f / (2 * H)) + LN_EPS);
            g_xn[(size_t)g * 2 * H + t]     = d0[gg] * rstd * lg0 + lb0;
            g_xn[(size_t)g * 2 * H + H + t] = d1[gg] * rstd * lg1 + lb1;
        }
    }
}

// ------- MLP: gelu(xn @ W1.T + b1) . W2 + b2 (coalesced via W1^T) ---------
__global__ void __launch_bounds__(256) mlp_k(
        const float* __restrict__ b1, const float* __restrict__ W2,
        const float* __restrict__ b2,
        float* __restrict__ out_stop, int G) {
    __shared__ __align__(16) float xsh[PG][2 * H];
    __shared__ float4 red4[32];
    int t = threadIdx.x;
    int g0 = blockIdx.x * PG;

    #pragma unroll
    for (int gg = 0; gg < PG; gg++) {
        int g = g0 + gg;
        xsh[gg][t]     = (g < G) ? g_xn[(size_t)g * 2 * H + t] : 0.f;
        xsh[gg][H + t] = (g < G) ? g_xn[(size_t)g * 2 * H + H + t] : 0.f;
    }
    __syncthreads();

    // thread t owns hidden unit t: acc[gg] += xsh[gg][j] * WT1[j][t]
    float acc[PG];
    #pragma unroll
    for (int gg = 0; gg < PG; gg++) acc[gg] = 0.f;
    #pragma unroll 8
    for (int j = 0; j < 2 * H; j++) {
        float wv = __ldg(g_WT1 + j * H + t);
        #pragma unroll
        for (int gg = 0; gg < PG; gg++)
            acc[gg] = fmaf(xsh[gg][j], wv, acc[gg]);
    }

    float bb = __ldg(b1 + t), wv2 = __ldg(W2 + t);
    float v[PG];
    #pragma unroll
    for (int gg = 0; gg < PG; gg++) {
        float a1 = acc[gg] + bb;
        float h1 = 0.5f * a1 * (1.0f + erff(a1 * 0.70710678118654752f));
        v[gg] = h1 * wv2;
    }
    float tot[PG];
    block_sum4(v, red4, tot);
    if (t == 0) {
        float bias = b2[0];
        #pragma unroll
        for (int gg = 0; gg < PG; gg++)
            if (g0 + gg < G) out_stop[g0 + gg] = tot[gg] + bias;
    }
}

// ---------------- launch ----------------
extern "C" void kernel_launch(void* const* d_in, const int* in_sizes, int n_in,
                              void* d_out, int out_size) {
    const float* edge_tokens = (const float*)d_in[0];
    const float* qtok        = (const float*)d_in[1];
    const int*   batch       = (const int*)d_in[2];
    const int*   sel         = (const int*)d_in[3];
    const float* W_edge      = (const float*)d_in[4];
    const float* W_query     = (const float*)d_in[5];
    const float* att_vec     = (const float*)d_in[6];
    const float* ln_g        = (const float*)d_in[7];
    const float* ln_b        = (const float*)d_in[8];
    const float* W1          = (const float*)d_in[9];
    const float* b1          = (const float*)d_in[10];
    const float* W2          = (const float*)d_in[11];
    const float* b2          = (const float*)d_in[12];

    int E = in_sizes[0] / H;
    int G = in_sizes[1] / H;

    float* out = (float*)d_out;
    float* out_edge   = out;            // [E]
    float* out_stop   = out + E;        // [G]
    float* out_pooled = out + E + G;    // [G*H]

    void* zp = nullptr;
    cudaGetSymbolAddress(&zp, g_z);
    cudaMemsetAsync(zp, 0, sizeof(Scratch));

    int nstop = (G + PG - 1) / PG;
    setup_k<<<226, 256>>>(W_edge, W_query, W1, att_vec, batch, E, G);
    qatt_k<<<(G + 7) / 8, 256>>>(qtok, G);
    pass1_k<<<NBLK_P1, 256>>>(edge_tokens, batch, sel, E);
    post_k<<<G + nstop, 256>>>(sel, qtok, ln_g, ln_b, out_edge, out_pooled, E, G);
    mlp_k<<<nstop, 256>>>(b1, W2, b2, out_stop, G);
}

// round 11
// speedup vs baseline: 1.0479x; 1.0479x over previous
#include <cuda_runtime.h>
#include <math.h>

#define H 256
#define MAXE 500000
#define MAXG 256
#define FRONTIER_BONUS 0.5f
#define LN_EPS 1e-5f
#define F32_EPS 1.1920929e-07f
#define LOG_EPS -15.942385152878742f   // ln(2^-23)
#define NBLK_P1 1184
#define STOPG 4

// ---------------- device scratch (single memset-able struct) ----------------
// __align__(16) REQUIRED: float4 (LDG.128) access to w_att and S.
struct __align__(16) Scratch {
    float    S[MAXG * H];     // segment sums of edge_tokens
    float    w_att[H];        // att_vec @ W_edge  (atomic partials)
    float    w_q[H];          // att_vec @ W_query (atomic partials)
    unsigned maxenc[MAXG];    // order-preserving-uint segment max (0 == -inf)
    int      cnt[MAXG];       // edges per graph
};
__device__ Scratch g_z;
__device__ float g_qatt[MAXG];   // fully overwritten each run
__device__ float g_att[MAXE];    // fully overwritten each run
__device__ float g_WTe[H * H];       // W_edge^T (fully overwritten)
__device__ float g_WT1[2 * H * H];   // W1^T     (fully overwritten)

// order-preserving float <-> uint; memset-0 acts as -infinity identity
__device__ __forceinline__ unsigned fenc(float f) {
    unsigned u = (unsigned)__float_as_int(f);
    return (u & 0x80000000u) ? ~u : (u | 0x80000000u);
}
__device__ __forceinline__ float fdec(unsigned u) {
    unsigned v = (u & 0x80000000u) ? (u & 0x7FFFFFFFu) : ~u;
    return __int_as_float((int)v);
}

// --- setup: w_att/w_q partials (blocks 0-31) + weight transposes (32-223) --
__global__ void __launch_bounds__(256) prew_k(const float* __restrict__ W_edge,
                       const float* __restrict__ W_query,
                       const float* __restrict__ W1,
                       const float* __restrict__ att_vec) {
    __shared__ float sh[32][33];
    int b = blockIdx.x, t = threadIdx.x;
    if (b < 32) {
        int m = b >> 4;                   // 0: W_edge, 1: W_query
        int c = b & 15;                   // row chunk of 16
        const float* W = m ? W_query : W_edge;
        int i0 = c * 16;
        float s = 0.f;
        #pragma unroll
        for (int i = 0; i < 16; i++)
            s = fmaf(__ldg(att_vec + i0 + i), __ldg(W + (i0 + i) * H + t), s);
        atomicAdd((m ? g_z.w_q : g_z.w_att) + t, s);
    } else if (b < 96) {
        // transpose W_edge [256 x 256] -> g_WTe: 8x8 tiles of 32x32
        int bt = b - 32;
        int ti = bt >> 3, tj = bt & 7;
        int x = t & 31, y = t >> 5;       // 32 x 8
        #pragma unroll
        for (int k = 0; k < 4; k++)
            sh[y + 8 * k][x] = __ldg(W_edge + (ti * 32 + y + 8 * k) * H + tj * 32 + x);
        __syncthreads();
        #pragma unroll
        for (int k = 0; k < 4; k++)
            g_WTe[(tj * 32 + y + 8 * k) * H + ti * 32 + x] = sh[x][y + 8 * k];
    } else {
        // transpose W1 [256 x 512] -> g_WT1 [512 x 256]: 8x16 = 128 tiles
        int bt = b - 96;
        int ti = bt >> 4, tj = bt & 15;
        int x = t & 31, y = t >> 5;
        #pragma unroll
        for (int k = 0; k < 4; k++)
            sh[y + 8 * k][x] = __ldg(W1 + (ti * 32 + y + 8 * k) * (2 * H) + tj * 32 + x);
        __syncthreads();
        #pragma unroll
        for (int k = 0; k < 4; k++)
            g_WT1[(tj * 32 + y + 8 * k) * H + ti * 32 + x] = sh[x][y + 8 * k];
    }
}

// ---------------- qatt[g] = question_tokens[g] . w_q ----------------
__global__ void __launch_bounds__(256) qatt_k(const float* __restrict__ qtok, int G) {
    int w = threadIdx.x >> 5, l = threadIdx.x & 31;
    int g = blockIdx.x * 8 + w;
    if (g >= G) return;
    float s = 0.f;
    #pragma unroll
    for (int k = 0; k < 8; k++) {
        int j = l + 32 * k;
        s = fmaf(qtok[(size_t)g * H + j], g_z.w_q[j], s);
    }
    #pragma unroll
    for (int sh = 16; sh; sh >>= 1) s += __shfl_xor_sync(0xFFFFFFFFu, s, sh);
    if (l == 0) g_qatt[g] = s;
}

// ---------------- main streaming pass: warp-per-edge, x4 unroll ----------
struct RunState {
    float4 a0, a1;
    float rmax, qcur;
    int cur, rcnt;
};

__device__ __forceinline__ void flush_run(RunState& st, int l) {
    if (st.cur < 0) return;
    float* Sp = &g_z.S[st.cur * H];
    atomicAdd(Sp + 4 * l + 0, st.a0.x);
    atomicAdd(Sp + 4 * l + 1, st.a0.y);
    atomicAdd(Sp + 4 * l + 2, st.a0.z);
    atomicAdd(Sp + 4 * l + 3, st.a0.w);
    atomicAdd(Sp + 128 + 4 * l + 0, st.a1.x);
    atomicAdd(Sp + 128 + 4 * l + 1, st.a1.y);
    atomicAdd(Sp + 128 + 4 * l + 2, st.a1.z);
    atomicAdd(Sp + 128 + 4 * l + 3, st.a1.w);
    if (l == 0) {
        atomicMax(&g_z.maxenc[st.cur], fenc(st.rmax));
        atomicAdd(&g_z.cnt[st.cur], st.rcnt);
    }
}

__device__ __forceinline__ void process_edge(RunState& st, int g, int selv,
                                             float4 x0, float4 x1,
                                             float4 wa0, float4 wa1,
                                             int e, int l) {
    if (g != st.cur) {
        flush_run(st, l);
        st.a0 = make_float4(0.f, 0.f, 0.f, 0.f);
        st.a1 = make_float4(0.f, 0.f, 0.f, 0.f);
        st.rmax = -INFINITY; st.rcnt = 0; st.cur = g;
        st.qcur = g_qatt[g];
    }
    st.a0.x += x0.x; st.a0.y += x0.y; st.a0.z += x0.z; st.a0.w += x0.w;
    st.a1.x += x1.x; st.a1.y += x1.y; st.a1.z += x1.z; st.a1.w += x1.w;
    float d = x0.x * wa0.x + x0.y * wa0.y + x0.z * wa0.z + x0.w * wa0.w
            + x1.x * wa1.x + x1.y * wa1.y + x1.z * wa1.z + x1.w * wa1.w;
    #pragma unroll
    for (int sh = 16; sh; sh >>= 1) d += __shfl_xor_sync(0xFFFFFFFFu, d, sh);
    float r = d + st.qcur;
    r = r > 0.f ? r : 0.2f * r;                       // LeakyReLU(0.2)
    if (selv == 0) r += FRONTIER_BONUS;               // candidate == frontier
    if (l == 0) g_att[e] = r;
    st.rmax = fmaxf(st.rmax, r);
    st.rcnt++;
}

__global__ void __launch_bounds__(256) pass1_k(const float* __restrict__ x,
                        const int* __restrict__ batch,
                        const int* __restrict__ sel,
                        int E) {
    int chunk = (E + NBLK_P1 - 1) / NBLK_P1;
    int lo = blockIdx.x * chunk;
    int hi = min(E, lo + chunk);
    int w = threadIdx.x >> 5, l = threadIdx.x & 31;

    const float4* wav = (const float4*)g_z.w_att;
    float4 wa0 = wav[l];
    float4 wa1 = wav[32 + l];

    RunState st;
    st.a0 = make_float4(0.f, 0.f, 0.f, 0.f);
    st.a1 = make_float4(0.f, 0.f, 0.f, 0.f);
    st.cur = -1; st.rcnt = 0; st.rmax = -INFINITY; st.qcur = 0.f;

    int e = lo + w;
    // x4 unroll: all loads unconditional and front-batched (8 LDG.128 in flight)
    for (; e + 24 < hi; e += 32) {
        int e1 = e + 8, e2 = e + 16, e3 = e + 24;
        int g0 = __ldg(batch + e);
        int g1 = __ldg(batch + e1);
        int g2 = __ldg(batch + e2);
        int g3 = __ldg(batch + e3);
        int s0 = __ldg(sel + e);
        int s1 = __ldg(sel + e1);
        int s2 = __ldg(sel + e2);
        int s3 = __ldg(sel + e3);
        const float4* r0 = (const float4*)(x + (size_t)e  * H);
        const float4* r1 = (const float4*)(x + (size_t)e1 * H);
        const float4* r2 = (const float4*)(x + (size_t)e2 * H);
        const float4* r3 = (const float4*)(x + (size_t)e3 * H);
        float4 xa0 = __ldg(r0 + l), xa1 = __ldg(r0 + 32 + l);
        float4 xb0 = __ldg(r1 + l), xb1 = __ldg(r1 + 32 + l);
        float4 xc0 = __ldg(r2 + l), xc1 = __ldg(r2 + 32 + l);
        float4 xd0 = __ldg(r3 + l), xd1 = __ldg(r3 + 32 + l);
        process_edge(st, g0, s0, xa0, xa1, wa0, wa1, e,  l);
        process_edge(st, g1, s1, xb0, xb1, wa0, wa1, e1, l);
        process_edge(st, g2, s2, xc0, xc1, wa0, wa1, e2, l);
        process_edge(st, g3, s3, xd0, xd1, wa0, wa1, e3, l);
    }
    for (; e < hi; e += 8) {
        int g = __ldg(batch + e);
        int s = __ldg(sel + e);
        const float4* row = (const float4*)(x + (size_t)e * H);
        float4 x0 = __ldg(row + l);
        float4 x1 = __ldg(row + 32 + l);
        process_edge(st, g, s, x0, x1, wa0, wa1, e, l);
    }
    flush_run(st, l);
}

// ---------------- fused post: softmax (blocks [0,G)) + full stop head -----
__device__ __forceinline__ int lower_bound_batch(const int* batch, int E, int key) {
    int lo = 0, hi = E;
    while (lo < hi) {
        int mid = (lo + hi) >> 1;
        if (__ldg(batch + mid) < key) lo = mid + 1; else hi = mid;
    }
    return lo;
}

__device__ __forceinline__ void block_sum4(float v[STOPG], float4* red4, float out[STOPG]) {
    int l = threadIdx.x & 31, w = threadIdx.x >> 5;
    #pragma unroll
    for (int sh = 16; sh; sh >>= 1) {
        #pragma unroll
        for (int gg = 0; gg < STOPG; gg++)
            v[gg] += __shfl_xor_sync(0xFFFFFFFFu, v[gg], sh);
    }
    if (l == 0) red4[w] = make_float4(v[0], v[1], v[2], v[3]);
    __syncthreads();
    if (w == 0) {
        float4 xv = (l < 8) ? red4[l] : make_float4(0.f, 0.f, 0.f, 0.f);
        #pragma unroll
        for (int sh = 4; sh; sh >>= 1) {
            xv.x += __shfl_xor_sync(0xFFFFFFFFu, xv.x, sh);
            xv.y += __shfl_xor_sync(0xFFFFFFFFu, xv.y, sh);
            xv.z += __shfl_xor_sync(0xFFFFFFFFu, xv.z, sh);
            xv.w += __shfl_xor_sync(0xFFFFFFFFu, xv.w, sh);
        }
        if (l == 0) red4[0] = xv;
    }
    __syncthreads();
    float4 r = red4[0];
    out[0] = r.x; out[1] = r.y; out[2] = r.z; out[3] = r.w;
    __syncthreads();
}

__global__ void __launch_bounds__(256) post_k(
        const int* __restrict__ batch, const int* __restrict__ sel,
        const float* __restrict__ qtok,
        const float* __restrict__ ln_g, const float* __restrict__ ln_b,
        const float* __restrict__ b1, const float* __restrict__ W2,
        const float* __restrict__ b2,
        float* __restrict__ out_edge, float* __restrict__ out_stop,
        float* __restrict__ out_pooled, int E, int G) {
    int t = threadIdx.x;
    int l = t & 31, w = t >> 5;

    if (blockIdx.x < (unsigned)G) {
        // -------- segment softmax + edge logits (lsum trick, no per-edge log)
        __shared__ float red[32];
        __shared__ float s_lsum;
        int g = blockIdx.x;
        int lo = lower_bound_batch(batch, E, g);
        int hi = lower_bound_batch(batch, E, g + 1);
        if (lo >= hi) return;

        float m = fdec(g_z.maxenc[g]);
        float s = 0.f;
        for (int e = lo + t; e < hi; e += 256)
            if (__ldg(sel + e) == 0) s += __expf(__ldg(g_att + e) - m);
        #pragma unroll
        for (int sh = 16; sh; sh >>= 1) s += __shfl_xor_sync(0xFFFFFFFFu, s, sh);
        if (l == 0) red[w] = s;
        __syncthreads();
        if (w == 0) {
            float v = (l < 8) ? red[l] : 0.f;
            #pragma unroll
            for (int sh = 4; sh; sh >>= 1) v += __shfl_xor_sync(0xFFFFFFFFu, v, sh);
            if (l == 0) s_lsum = __logf(fmaxf(v, F32_EPS));
        }
        __syncthreads();
        float lsum = s_lsum;
        // log(max(p,eps)) = max(log p, log eps); log p = (att-m) - lsum
        for (int e = lo + t; e < hi; e += 256) {
            float o = LOG_EPS;
            if (__ldg(sel + e) == 0)
                o = fmaxf(__ldg(g_att + e) - m - lsum, LOG_EPS);
            out_edge[e] = o;
        }
    } else {
        // -------- stop head: STOPG graphs/block, transposed-broadcast matvecs
        __shared__ __align__(16) float ssh[STOPG][H];       // S/denom
        __shared__ __align__(16) float xsh[STOPG][2 * H];   // layernormed inputs
        __shared__ float4 red4[32];
        int g0 = (blockIdx.x - G) * STOPG;

        #pragma unroll
        for (int gg = 0; gg < STOPG; gg++) {
            int g = g0 + gg;
            float v = 0.f;
            if (g < G) {
                float denom = fmaxf((float)g_z.cnt[g], 1.0f);
                v = g_z.S[g * H + t] / denom;
            }
            ssh[gg][t] = v;
        }
        __syncthreads();

        // matvec1: thread t owns output row t: acc += ssh[j] * WTe[j][t]
        // WTe load coalesced; ssh broadcast; no shuffles in loop.
        float acc[STOPG];
        #pragma unroll
        for (int gg = 0; gg < STOPG; gg++) acc[gg] = 0.f;
        #pragma unroll 8
        for (int j = 0; j < H; j++) {
            float wv = __ldg(g_WTe + j * H + t);
            #pragma unroll
            for (int gg = 0; gg < STOPG; gg++)
                acc[gg] = fmaf(ssh[gg][j], wv, acc[gg]);
        }

        float pe[STOPG], qv[STOPG];
        #pragma unroll
        for (int gg = 0; gg < STOPG; gg++) {
            int g = g0 + gg;
            pe[gg] = acc[gg];
            qv[gg] = (g < G) ? qtok[(size_t)g * H + t] : 0.f;
            if (g < G) out_pooled[(size_t)g * H + t] = pe[gg];
        }

        // LayerNorm over 512 per graph
        float v[STOPG], mu[STOPG], var[STOPG];
        #pragma unroll
        for (int gg = 0; gg < STOPG; gg++) v[gg] = pe[gg] + qv[gg];
        block_sum4(v, red4, mu);
        float d0[STOPG], d1[STOPG];
        #pragma unroll
        for (int gg = 0; gg < STOPG; gg++) {
            mu[gg] *= (1.0f / (2 * H));
            d0[gg] = pe[gg] - mu[gg];
            d1[gg] = qv[gg] - mu[gg];
            v[gg] = d0[gg] * d0[gg] + d1[gg] * d1[gg];
        }
        block_sum4(v, red4, var);
        float lg0 = ln_g[t], lb0 = ln_b[t], lg1 = ln_g[H + t], lb1 = ln_b[H + t];
        #pragma unroll
        for (int gg = 0; gg < STOPG; gg++) {
            float rstd = rsqrtf(var[gg] * (1.0f / (2 * H)) + LN_EPS);
            xsh[gg][t]     = d0[gg] * rstd * lg0 + lb0;
            xsh[gg][H + t] = d1[gg] * rstd * lg1 + lb1;
        }
        __syncthreads();

        // matvec2: thread t owns hidden unit t: acc += xsh[j] * WT1[j][t]
        #pragma unroll
        for (int gg = 0; gg < STOPG; gg++) acc[gg] = 0.f;
        #pragma unroll 8
        for (int j = 0; j < 2 * H; j++) {
            float wv = __ldg(g_WT1 + j * H + t);
            #pragma unroll
            for (int gg = 0; gg < STOPG; gg++)
                acc[gg] = fmaf(xsh[gg][j], wv, acc[gg]);
        }

        float bb = __ldg(b1 + t), wv2 = __ldg(W2 + t);
        #pragma unroll
        for (int gg = 0; gg < STOPG; gg++) {
            float a1 = acc[gg] + bb;
            float h1 = 0.5f * a1 * (1.0f + erff(a1 * 0.70710678118654752f));
            v[gg] = h1 * wv2;
        }
        float tot[STOPG];
        block_sum4(v, red4, tot);
        if (t == 0) {
            float bias = b2[0];
            #pragma unroll
            for (int gg = 0; gg < STOPG; gg++)
                if (g0 + gg < G) out_stop[g0 + gg] = tot[gg] + bias;
        }
    }
}

// ---------------- launch ----------------
extern "C" void kernel_launch(void* const* d_in, const int* in_sizes, int n_in,
                              void* d_out, int out_size) {
    const float* edge_tokens = (const float*)d_in[0];
    const float* qtok        = (const float*)d_in[1];
    const int*   batch       = (const int*)d_in[2];
    const int*   sel         = (const int*)d_in[3];
    const float* W_edge      = (const float*)d_in[4];
    const float* W_query     = (const float*)d_in[5];
    const float* att_vec     = (const float*)d_in[6];
    const float* ln_g        = (const float*)d_in[7];
    const float* ln_b        = (const float*)d_in[8];
    const float* W1          = (const float*)d_in[9];
    const float* b1          = (const float*)d_in[10];
    const float* W2          = (const float*)d_in[11];
    const float* b2          = (const float*)d_in[12];

    int E = in_sizes[0] / H;
    int G = in_sizes[1] / H;

    float* out = (float*)d_out;
    float* out_edge   = out;            // [E]
    float* out_stop   = out + E;        // [G]
    float* out_pooled = out + E + G;    // [G*H]

    void* zp = nullptr;
    cudaGetSymbolAddress(&zp, g_z);
    cudaMemsetAsync(zp, 0, sizeof(Scratch));

    int nstop = (G + STOPG - 1) / STOPG;
    prew_k<<<224, 256>>>(W_edge, W_query, W1, att_vec);
    qatt_k<<<(G + 7) / 8, 256>>>(qtok, G);
    pass1_k<<<NBLK_P1, 256>>>(edge_tokens, batch, sel, E);
    post_k<<<G + nstop, 256>>>(batch, sel, qtok, ln_g, ln_b, b1, W2, b2,
                               out_edge, out_stop, out_pooled, E, G);
}

// round 12
// speedup vs baseline: 1.1070x; 1.0564x over previous
#include <cuda_runtime.h>
#include <math.h>

#define H 256
#define MAXE 500000
#define MAXG 256
#define FRONTIER_BONUS 0.5f
#define LN_EPS 1e-5f
#define F32_EPS 1.1920929e-07f
#define LOG_EPS -15.942385152878742f   // ln(2^-23)
#define NBLK_P1 1184
#define STOPG 4

// ---------------- device scratch (single memset-able struct) ----------------
// __align__(16) REQUIRED: float4 (LDG.128) access to w_att and S.
struct __align__(16) Scratch {
    float    S[MAXG * H];     // segment sums of edge_tokens
    float    w_att[H];        // att_vec @ W_edge  (atomic partials)
    float    w_q[H];          // att_vec @ W_query (atomic partials)
    unsigned maxenc[MAXG];    // order-preserving-uint segment max (0 == -inf)
    int      cnt[MAXG];       // edges per graph
};
__device__ Scratch g_z;
__device__ float g_qatt[MAXG];       // fully overwritten each run
__device__ float g_att[MAXE];        // fully overwritten each run
__device__ int   g_seg[MAXG + 1];    // segment bounds (fully overwritten)
__device__ float g_WTe[H * H];       // W_edge^T (fully overwritten)
__device__ float g_WT1[2 * H * H];   // W1^T     (fully overwritten)

// order-preserving float <-> uint; memset-0 acts as -infinity identity
__device__ __forceinline__ unsigned fenc(float f) {
    unsigned u = (unsigned)__float_as_int(f);
    return (u & 0x80000000u) ? ~u : (u | 0x80000000u);
}
__device__ __forceinline__ float fdec(unsigned u) {
    unsigned v = (u & 0x80000000u) ? (u & 0x7FFFFFFFu) : ~u;
    return __int_as_float((int)v);
}

// --- setup: w_att/w_q partials (0-31) + transposes (32-223) + seg (224-225)
__global__ void __launch_bounds__(256) prew_k(const float* __restrict__ W_edge,
                       const float* __restrict__ W_query,
                       const float* __restrict__ W1,
                       const float* __restrict__ att_vec,
                       const int* __restrict__ batch, int E, int G) {
    __shared__ float sh[32][33];
    int b = blockIdx.x, t = threadIdx.x;
    if (b < 32) {
        int m = b >> 4;                   // 0: W_edge, 1: W_query
        int c = b & 15;                   // row chunk of 16
        const float* W = m ? W_query : W_edge;
        int i0 = c * 16;
        float s = 0.f;
        #pragma unroll
        for (int i = 0; i < 16; i++)
            s = fmaf(__ldg(att_vec + i0 + i), __ldg(W + (i0 + i) * H + t), s);
        atomicAdd((m ? g_z.w_q : g_z.w_att) + t, s);
    } else if (b < 96) {
        // transpose W_edge [256 x 256] -> g_WTe: 8x8 tiles of 32x32
        int bt = b - 32;
        int ti = bt >> 3, tj = bt & 7;
        int x = t & 31, y = t >> 5;       // 32 x 8
        #pragma unroll
        for (int k = 0; k < 4; k++)
            sh[y + 8 * k][x] = __ldg(W_edge + (ti * 32 + y + 8 * k) * H + tj * 32 + x);
        __syncthreads();
        #pragma unroll
        for (int k = 0; k < 4; k++)
            g_WTe[(tj * 32 + y + 8 * k) * H + ti * 32 + x] = sh[x][y + 8 * k];
    } else if (b < 224) {
        // transpose W1 [256 x 512] -> g_WT1 [512 x 256]: 8x16 = 128 tiles
        int bt = b - 96;
        int ti = bt >> 4, tj = bt & 15;
        int x = t & 31, y = t >> 5;
        #pragma unroll
        for (int k = 0; k < 4; k++)
            sh[y + 8 * k][x] = __ldg(W1 + (ti * 32 + y + 8 * k) * (2 * H) + tj * 32 + x);
        __syncthreads();
        #pragma unroll
        for (int k = 0; k < 4; k++)
            g_WT1[(tj * 32 + y + 8 * k) * H + ti * 32 + x] = sh[x][y + 8 * k];
    } else {
        // segment bounds: g_seg[i] = lower_bound(batch, i)
        int i = (b - 224) * 256 + t;
        if (i > G) return;
        int lo = 0, hi = E;
        while (lo < hi) {
            int mid = (lo + hi) >> 1;
            if (__ldg(batch + mid) < i) lo = mid + 1; else hi = mid;
        }
        g_seg[i] = lo;
    }
}

// ---------------- qatt[g] = question_tokens[g] . w_q ----------------
__global__ void __launch_bounds__(256) qatt_k(const float* __restrict__ qtok, int G) {
    int w = threadIdx.x >> 5, l = threadIdx.x & 31;
    int g = blockIdx.x * 8 + w;
    if (g >= G) return;
    float s = 0.f;
    #pragma unroll
    for (int k = 0; k < 8; k++) {
        int j = l + 32 * k;
        s = fmaf(qtok[(size_t)g * H + j], g_z.w_q[j], s);
    }
    #pragma unroll
    for (int sh = 16; sh; sh >>= 1) s += __shfl_xor_sync(0xFFFFFFFFu, s, sh);
    if (l == 0) g_qatt[g] = s;
}

// ---------------- main streaming pass: warp-per-edge, x4 unroll ----------
struct RunState {
    float4 a0, a1;
    float rmax, qcur;
    int cur, rcnt;
};

__device__ __forceinline__ void flush_run(RunState& st, int l) {
    if (st.cur < 0) return;
    float* Sp = &g_z.S[st.cur * H];
    atomicAdd(Sp + 4 * l + 0, st.a0.x);
    atomicAdd(Sp + 4 * l + 1, st.a0.y);
    atomicAdd(Sp + 4 * l + 2, st.a0.z);
    atomicAdd(Sp + 4 * l + 3, st.a0.w);
    atomicAdd(Sp + 128 + 4 * l + 0, st.a1.x);
    atomicAdd(Sp + 128 + 4 * l + 1, st.a1.y);
    atomicAdd(Sp + 128 + 4 * l + 2, st.a1.z);
    atomicAdd(Sp + 128 + 4 * l + 3, st.a1.w);
    if (l == 0) {
        atomicMax(&g_z.maxenc[st.cur], fenc(st.rmax));
        atomicAdd(&g_z.cnt[st.cur], st.rcnt);
    }
}

__device__ __forceinline__ void process_edge(RunState& st, int g, int selv,
                                             float4 x0, float4 x1,
                                             float4 wa0, float4 wa1,
                                             int e, int l) {
    if (g != st.cur) {
        flush_run(st, l);
        st.a0 = make_float4(0.f, 0.f, 0.f, 0.f);
        st.a1 = make_float4(0.f, 0.f, 0.f, 0.f);
        st.rmax = -INFINITY; st.rcnt = 0; st.cur = g;
        st.qcur = g_qatt[g];
    }
    st.a0.x += x0.x; st.a0.y += x0.y; st.a0.z += x0.z; st.a0.w += x0.w;
    st.a1.x += x1.x; st.a1.y += x1.y; st.a1.z += x1.z; st.a1.w += x1.w;
    float d = x0.x * wa0.x + x0.y * wa0.y + x0.z * wa0.z + x0.w * wa0.w
            + x1.x * wa1.x + x1.y * wa1.y + x1.z * wa1.z + x1.w * wa1.w;
    #pragma unroll
    for (int sh = 16; sh; sh >>= 1) d += __shfl_xor_sync(0xFFFFFFFFu, d, sh);
    float r = d + st.qcur;
    r = r > 0.f ? r : 0.2f * r;                       // LeakyReLU(0.2)
    if (selv == 0) r += FRONTIER_BONUS;               // candidate == frontier
    if (l == 0) g_att[e] = r;
    st.rmax = fmaxf(st.rmax, r);
    st.rcnt++;
}

__global__ void __launch_bounds__(256) pass1_k(const float* __restrict__ x,
                        const int* __restrict__ batch,
                        const int* __restrict__ sel,
                        int E) {
    int chunk = (E + NBLK_P1 - 1) / NBLK_P1;
    int lo = blockIdx.x * chunk;
    int hi = min(E, lo + chunk);
    int w = threadIdx.x >> 5, l = threadIdx.x & 31;

    const float4* wav = (const float4*)g_z.w_att;
    float4 wa0 = wav[l];
    float4 wa1 = wav[32 + l];

    RunState st;
    st.a0 = make_float4(0.f, 0.f, 0.f, 0.f);
    st.a1 = make_float4(0.f, 0.f, 0.f, 0.f);
    st.cur = -1; st.rcnt = 0; st.rmax = -INFINITY; st.qcur = 0.f;

    int e = lo + w;
    // x4 unroll: all loads unconditional and front-batched (8 LDG.128 in flight)
    for (; e + 24 < hi; e += 32) {
        int e1 = e + 8, e2 = e + 16, e3 = e + 24;
        int g0 = __ldg(batch + e);
        int g1 = __ldg(batch + e1);
        int g2 = __ldg(batch + e2);
        int g3 = __ldg(batch + e3);
        int s0 = __ldg(sel + e);
        int s1 = __ldg(sel + e1);
        int s2 = __ldg(sel + e2);
        int s3 = __ldg(sel + e3);
        const float4* r0 = (const float4*)(x + (size_t)e  * H);
        const float4* r1 = (const float4*)(x + (size_t)e1 * H);
        const float4* r2 = (const float4*)(x + (size_t)e2 * H);
        const float4* r3 = (const float4*)(x + (size_t)e3 * H);
        float4 xa0 = __ldg(r0 + l), xa1 = __ldg(r0 + 32 + l);
        float4 xb0 = __ldg(r1 + l), xb1 = __ldg(r1 + 32 + l);
        float4 xc0 = __ldg(r2 + l), xc1 = __ldg(r2 + 32 + l);
        float4 xd0 = __ldg(r3 + l), xd1 = __ldg(r3 + 32 + l);
        process_edge(st, g0, s0, xa0, xa1, wa0, wa1, e,  l);
        process_edge(st, g1, s1, xb0, xb1, wa0, wa1, e1, l);
        process_edge(st, g2, s2, xc0, xc1, wa0, wa1, e2, l);
        process_edge(st, g3, s3, xd0, xd1, wa0, wa1, e3, l);
    }
    for (; e < hi; e += 8) {
        int g = __ldg(batch + e);
        int s = __ldg(sel + e);
        const float4* row = (const float4*)(x + (size_t)e * H);
        float4 x0 = __ldg(row + l);
        float4 x1 = __ldg(row + 32 + l);
        process_edge(st, g, s, x0, x1, wa0, wa1, e, l);
    }
    flush_run(st, l);
}

// ---------------- fused post: softmax (blocks [0,G)) + full stop head -----
__device__ __forceinline__ void block_sum4(float v[STOPG], float4* red4, float out[STOPG]) {
    int l = threadIdx.x & 31, w = threadIdx.x >> 5;
    #pragma unroll
    for (int sh = 16; sh; sh >>= 1) {
        #pragma unroll
        for (int gg = 0; gg < STOPG; gg++)
            v[gg] += __shfl_xor_sync(0xFFFFFFFFu, v[gg], sh);
    }
    if (l == 0) red4[w] = make_float4(v[0], v[1], v[2], v[3]);
    __syncthreads();
    if (w == 0) {
        float4 xv = (l < 8) ? red4[l] : make_float4(0.f, 0.f, 0.f, 0.f);
        #pragma unroll
        for (int sh = 4; sh; sh >>= 1) {
            xv.x += __shfl_xor_sync(0xFFFFFFFFu, xv.x, sh);
            xv.y += __shfl_xor_sync(0xFFFFFFFFu, xv.y, sh);
            xv.z += __shfl_xor_sync(0xFFFFFFFFu, xv.z, sh);
            xv.w += __shfl_xor_sync(0xFFFFFFFFu, xv.w, sh);
        }
        if (l == 0) red4[0] = xv;
    }
    __syncthreads();
    float4 r = red4[0];
    out[0] = r.x; out[1] = r.y; out[2] = r.z; out[3] = r.w;
    __syncthreads();
}

__global__ void __launch_bounds__(256) post_k(
        const int* __restrict__ sel,
        const float* __restrict__ qtok,
        const float* __restrict__ ln_g, const float* __restrict__ ln_b,
        const float* __restrict__ b1, const float* __restrict__ W2,
        const float* __restrict__ b2,
        float* __restrict__ out_edge, float* __restrict__ out_stop,
        float* __restrict__ out_pooled, int E, int G) {
    int t = threadIdx.x;
    int l = t & 31, w = t >> 5;

    if (blockIdx.x < (unsigned)G) {
        // -------- segment softmax + edge logits (precomputed bounds) ------
        __shared__ float red[32];
        __shared__ float s_lsum;
        int g = blockIdx.x;
        int lo = __ldg(g_seg + g);
        int hi = __ldg(g_seg + g + 1);
        if (lo >= hi) return;

        float m = fdec(g_z.maxenc[g]);
        float s = 0.f;
        for (int e = lo + t; e < hi; e += 256)
            if (__ldg(sel + e) == 0) s += __expf(__ldg(g_att + e) - m);
        #pragma unroll
        for (int sh = 16; sh; sh >>= 1) s += __shfl_xor_sync(0xFFFFFFFFu, s, sh);
        if (l == 0) red[w] = s;
        __syncthreads();
        if (w == 0) {
            float v = (l < 8) ? red[l] : 0.f;
            #pragma unroll
            for (int sh = 4; sh; sh >>= 1) v += __shfl_xor_sync(0xFFFFFFFFu, v, sh);
            if (l == 0) s_lsum = __logf(fmaxf(v, F32_EPS));
        }
        __syncthreads();
        float lsum = s_lsum;
        // log(max(p,eps)) = max(log p, log eps); log p = (att-m) - lsum
        for (int e = lo + t; e < hi; e += 256) {
            float o = LOG_EPS;
            if (__ldg(sel + e) == 0)
                o = fmaxf(__ldg(g_att + e) - m - lsum, LOG_EPS);
            out_edge[e] = o;
        }
    } else {
        // -------- stop head: STOPG graphs/block, EXPLICIT 32-deep batching
        __shared__ __align__(16) float ssh[STOPG][H];       // S/denom
        __shared__ __align__(16) float xsh[STOPG][2 * H];   // layernormed inputs
        __shared__ float4 red4[32];
        int g0 = (blockIdx.x - G) * STOPG;

        #pragma unroll
        for (int gg = 0; gg < STOPG; gg++) {
            int g = g0 + gg;
            float v = 0.f;
            if (g < G) {
                float denom = fmaxf((float)g_z.cnt[g], 1.0f);
                v = g_z.S[g * H + t] / denom;
            }
            ssh[gg][t] = v;
        }
        __syncthreads();

        // matvec1: thread t owns output row t: acc += ssh[j] * WTe[j][t]
        // 32 loads issued up front per batch -> latency hidden by MLP depth
        float acc[STOPG];
        #pragma unroll
        for (int gg = 0; gg < STOPG; gg++) acc[gg] = 0.f;
        for (int j0 = 0; j0 < H; j0 += 32) {
            float wv[32];
            #pragma unroll
            for (int jj = 0; jj < 32; jj++)
                wv[jj] = __ldg(g_WTe + (j0 + jj) * H + t);
            #pragma unroll
            for (int jj = 0; jj < 32; jj++) {
                #pragma unroll
                for (int gg = 0; gg < STOPG; gg++)
                    acc[gg] = fmaf(ssh[gg][j0 + jj], wv[jj], acc[gg]);
            }
        }

        float pe[STOPG], qv[STOPG];
        #pragma unroll
        for (int gg = 0; gg < STOPG; gg++) {
            int g = g0 + gg;
            pe[gg] = acc[gg];
            qv[gg] = (g < G) ? qtok[(size_t)g * H + t] : 0.f;
            if (g < G) out_pooled[(size_t)g * H + t] = pe[gg];
        }

        // LayerNorm over 512 per graph
        float v[STOPG], mu[STOPG], var[STOPG];
        #pragma unroll
        for (int gg = 0; gg < STOPG; gg++) v[gg] = pe[gg] + qv[gg];
        block_sum4(v, red4, mu);
        float d0[STOPG], d1[STOPG];
        #pragma unroll
        for (int gg = 0; gg < STOPG; gg++) {
            mu[gg] *= (1.0f / (2 * H));
            d0[gg] = pe[gg] - mu[gg];
            d1[gg] = qv[gg] - mu[gg];
            v[gg] = d0[gg] * d0[gg] + d1[gg] * d1[gg];
        }
        block_sum4(v, red4, var);
        float lg0 = ln_g[t], lb0 = ln_b[t], lg1 = ln_g[H + t], lb1 = ln_b[H + t];
        #pragma unroll
        for (int gg = 0; gg < STOPG; gg++) {
            float rstd = rsqrtf(var[gg] * (1.0f / (2 * H)) + LN_EPS);
            xsh[gg][t]     = d0[gg] * rstd * lg0 + lb0;
            xsh[gg][H + t] = d1[gg] * rstd * lg1 + lb1;
        }
        __syncthreads();

        // matvec2: thread t owns hidden unit t: acc += xsh[j] * WT1[j][t]
        #pragma unroll
        for (int gg = 0; gg < STOPG; gg++) acc[gg] = 0.f;
        for (int j0 = 0; j0 < 2 * H; j0 += 32) {
            float wv[32];
            #pragma unroll
            for (int jj = 0; jj < 32; jj++)
                wv[jj] = __ldg(g_WT1 + (j0 + jj) * H + t);
            #pragma unroll
            for (int jj = 0; jj < 32; jj++) {
                #pragma unroll
                for (int gg = 0; gg < STOPG; gg++)
                    acc[gg] = fmaf(xsh[gg][j0 + jj], wv[jj], acc[gg]);
            }
        }

        float bb = __ldg(b1 + t), wv2 = __ldg(W2 + t);
        #pragma unroll
        for (int gg = 0; gg < STOPG; gg++) {
            float a1 = acc[gg] + bb;
            float h1 = 0.5f * a1 * (1.0f + erff(a1 * 0.70710678118654752f));
            v[gg] = h1 * wv2;
        }
        float tot[STOPG];
        block_sum4(v, red4, tot);
        if (t == 0) {
            float bias = b2[0];
            #pragma unroll
            for (int gg = 0; gg < STOPG; gg++)
                if (g0 + gg < G) out_stop[g0 + gg] = tot[gg] + bias;
        }
    }
}

// ---------------- launch ----------------
extern "C" void kernel_launch(void* const* d_in, const int* in_sizes, int n_in,
                              void* d_out, int out_size) {
    const float* edge_tokens = (const float*)d_in[0];
    const float* qtok        = (const float*)d_in[1];
    const int*   batch       = (const int*)d_in[2];
    const int*   sel         = (const int*)d_in[3];
    const float* W_edge      = (const float*)d_in[4];
    const float* W_query     = (const float*)d_in[5];
    const float* att_vec     = (const float*)d_in[6];
    const float* ln_g        = (const float*)d_in[7];
    const float* ln_b        = (const float*)d_in[8];
    const float* W1          = (const float*)d_in[9];
    const float* b1          = (const float*)d_in[10];
    const float* W2          = (const float*)d_in[11];
    const float* b2          = (const float*)d_in[12];

    int E = in_sizes[0] / H;
    int G = in_sizes[1] / H;

    float* out = (float*)d_out;
    float* out_edge   = out;            // [E]
    float* out_stop   = out + E;        // [G]
    float* out_pooled = out + E + G;    // [G*H]

    void* zp = nullptr;
    cudaGetSymbolAddress(&zp, g_z);
    cudaMemsetAsync(zp, 0, sizeof(Scratch));

    int nstop = (G + STOPG - 1) / STOPG;
    prew_k<<<226, 256>>>(W_edge, W_query, W1, att_vec, batch, E, G);
    qatt_k<<<(G + 7) / 8, 256>>>(qtok, G);
    pass1_k<<<NBLK_P1, 256>>>(edge_tokens, batch, sel, E);
    post_k<<<G + nstop, 256>>>(sel, qtok, ln_g, ln_b, b1, W2, b2,
                               out_edge, out_stop, out_pooled, E, G);
}

// round 13
// speedup vs baseline: 1.4234x; 1.2858x over previous
#include <cuda_runtime.h>
#include <math.h>

#define H 256
#define MAXE 500000
#define MAXG 256
#define FRONTIER_BONUS 0.5f
#define LN_EPS 1e-5f
#define F32_EPS 1.1920929e-07f
#define LOG_EPS -15.942385152878742f   // ln(2^-23)
#define NBLK_P1 1184
#define STOPG 4

// ---------------- device scratch (single memset-able struct) ----------------
// __align__(16) REQUIRED: float4 (LDG.128) access to w_att and S.
struct __align__(16) Scratch {
    float    S[MAXG * H];     // segment sums of edge_tokens
    float    w_att[H];        // att_vec @ W_edge  (atomic partials)
    float    w_q[H];          // att_vec @ W_query (atomic partials)
    unsigned maxenc[MAXG];    // order-preserving-uint segment max (0 == -inf)
    int      cnt[MAXG];       // edges per graph
};
__device__ Scratch g_z;
__device__ float g_qatt[MAXG];       // fully overwritten each run
__device__ float g_att[MAXE];        // fully overwritten each run
__device__ int   g_seg[MAXG + 1];    // segment bounds (fully overwritten)
// Interleaved weights: WI4[c/4 * 256 + r] = {W[r][c], W[r][c+1], W[r][c+2], W[r][c+3]}
// -> thread t reading row t's j-th quad hits address (j*256+t): coalesced.
__device__ float4 g_WeI[(H / 4) * H];          // W_edge interleaved  (64*256)
__device__ float4 g_W1I[(2 * H / 4) * H];      // W1 interleaved      (128*256)

// order-preserving float <-> uint; memset-0 acts as -infinity identity
__device__ __forceinline__ unsigned fenc(float f) {
    unsigned u = (unsigned)__float_as_int(f);
    return (u & 0x80000000u) ? ~u : (u | 0x80000000u);
}
__device__ __forceinline__ float fdec(unsigned u) {
    unsigned v = (u & 0x80000000u) ? (u & 0x7FFFFFFFu) : ~u;
    return __int_as_float((int)v);
}

// --- setup: w_att/w_q partials (0-31) + weight interleave (32-223) + seg ---
__global__ void __launch_bounds__(256) prew_k(const float* __restrict__ W_edge,
                       const float* __restrict__ W_query,
                       const float* __restrict__ W1,
                       const float* __restrict__ att_vec,
                       const int* __restrict__ batch, int E, int G) {
    __shared__ float sh[32][33];
    int b = blockIdx.x, t = threadIdx.x;
    if (b < 32) {
        int m = b >> 4;                   // 0: W_edge, 1: W_query
        int c = b & 15;                   // row chunk of 16
        const float* W = m ? W_query : W_edge;
        int i0 = c * 16;
        float s = 0.f;
        #pragma unroll
        for (int i = 0; i < 16; i++)
            s = fmaf(__ldg(att_vec + i0 + i), __ldg(W + (i0 + i) * H + t), s);
        atomicAdd((m ? g_z.w_q : g_z.w_att) + t, s);
    } else if (b < 96) {
        // interleave W_edge [256 x 256]: 8x8 tiles of 32x32
        int bt = b - 32;
        int ti = bt >> 3, tj = bt & 7;    // row tile, col tile
        int x = t & 31, y = t >> 5;       // 32 x 8
        #pragma unroll
        for (int k = 0; k < 4; k++)
            sh[y + 8 * k][x] = __ldg(W_edge + (ti * 32 + y + 8 * k) * H + tj * 32 + x);
        __syncthreads();
        int rl = t & 31, jl = t >> 5;     // local row, local col-quad
        float4 v = make_float4(sh[rl][jl * 4 + 0], sh[rl][jl * 4 + 1],
                               sh[rl][jl * 4 + 2], sh[rl][jl * 4 + 3]);
        g_WeI[(tj * 8 + jl) * H + ti * 32 + rl] = v;
    } else if (b < 224) {
        // interleave W1 [256 x 512]: 8x16 = 128 tiles of 32x32
        int bt = b - 96;
        int ti = bt >> 4, tj = bt & 15;
        int x = t & 31, y = t >> 5;
        #pragma unroll
        for (int k = 0; k < 4; k++)
            sh[y + 8 * k][x] = __ldg(W1 + (ti * 32 + y + 8 * k) * (2 * H) + tj * 32 + x);
        __syncthreads();
        int rl = t & 31, jl = t >> 5;
        float4 v = make_float4(sh[rl][jl * 4 + 0], sh[rl][jl * 4 + 1],
                               sh[rl][jl * 4 + 2], sh[rl][jl * 4 + 3]);
        g_W1I[(tj * 8 + jl) * H + ti * 32 + rl] = v;
    } else {
        // segment bounds: g_seg[i] = lower_bound(batch, i)
        int i = (b - 224) * 256 + t;
        if (i > G) return;
        int lo = 0, hi = E;
        while (lo < hi) {
            int mid = (lo + hi) >> 1;
            if (__ldg(batch + mid) < i) lo = mid + 1; else hi = mid;
        }
        g_seg[i] = lo;
    }
}

// ---------------- qatt[g] = question_tokens[g] . w_q ----------------
__global__ void __launch_bounds__(256) qatt_k(const float* __restrict__ qtok, int G) {
    int w = threadIdx.x >> 5, l = threadIdx.x & 31;
    int g = blockIdx.x * 8 + w;
    if (g >= G) return;
    float s = 0.f;
    #pragma unroll
    for (int k = 0; k < 8; k++) {
        int j = l + 32 * k;
        s = fmaf(qtok[(size_t)g * H + j], g_z.w_q[j], s);
    }
    #pragma unroll
    for (int sh = 16; sh; sh >>= 1) s += __shfl_xor_sync(0xFFFFFFFFu, s, sh);
    if (l == 0) g_qatt[g] = s;
}

// ---------------- main streaming pass: warp-per-edge, x4 unroll ----------
struct RunState {
    float4 a0, a1;
    float rmax, qcur;
    int cur, rcnt;
};

__device__ __forceinline__ void flush_run(RunState& st, int l) {
    if (st.cur < 0) return;
    float* Sp = &g_z.S[st.cur * H];
    atomicAdd(Sp + 4 * l + 0, st.a0.x);
    atomicAdd(Sp + 4 * l + 1, st.a0.y);
    atomicAdd(Sp + 4 * l + 2, st.a0.z);
    atomicAdd(Sp + 4 * l + 3, st.a0.w);
    atomicAdd(Sp + 128 + 4 * l + 0, st.a1.x);
    atomicAdd(Sp + 128 + 4 * l + 1, st.a1.y);
    atomicAdd(Sp + 128 + 4 * l + 2, st.a1.z);
    atomicAdd(Sp + 128 + 4 * l + 3, st.a1.w);
    if (l == 0) {
        atomicMax(&g_z.maxenc[st.cur], fenc(st.rmax));
        atomicAdd(&g_z.cnt[st.cur], st.rcnt);
    }
}

__device__ __forceinline__ void process_edge(RunState& st, int g, int selv,
                                             float4 x0, float4 x1,
                                             float4 wa0, float4 wa1,
                                             int e, int l) {
    if (g != st.cur) {
        flush_run(st, l);
        st.a0 = make_float4(0.f, 0.f, 0.f, 0.f);
        st.a1 = make_float4(0.f, 0.f, 0.f, 0.f);
        st.rmax = -INFINITY; st.rcnt = 0; st.cur = g;
        st.qcur = g_qatt[g];
    }
    st.a0.x += x0.x; st.a0.y += x0.y; st.a0.z += x0.z; st.a0.w += x0.w;
    st.a1.x += x1.x; st.a1.y += x1.y; st.a1.z += x1.z; st.a1.w += x1.w;
    float d = x0.x * wa0.x + x0.y * wa0.y + x0.z * wa0.z + x0.w * wa0.w
            + x1.x * wa1.x + x1.y * wa1.y + x1.z * wa1.z + x1.w * wa1.w;
    #pragma unroll
    for (int sh = 16; sh; sh >>= 1) d += __shfl_xor_sync(0xFFFFFFFFu, d, sh);
    float r = d + st.qcur;
    r = r > 0.f ? r : 0.2f * r;                       // LeakyReLU(0.2)
    if (selv == 0) r += FRONTIER_BONUS;               // candidate == frontier
    if (l == 0) g_att[e] = r;
    st.rmax = fmaxf(st.rmax, r);
    st.rcnt++;
}

__global__ void __launch_bounds__(256) pass1_k(const float* __restrict__ x,
                        const int* __restrict__ batch,
                        const int* __restrict__ sel,
                        int E) {
    int chunk = (E + NBLK_P1 - 1) / NBLK_P1;
    int lo = blockIdx.x * chunk;
    int hi = min(E, lo + chunk);
    int w = threadIdx.x >> 5, l = threadIdx.x & 31;

    const float4* wav = (const float4*)g_z.w_att;
    float4 wa0 = wav[l];
    float4 wa1 = wav[32 + l];

    RunState st;
    st.a0 = make_float4(0.f, 0.f, 0.f, 0.f);
    st.a1 = make_float4(0.f, 0.f, 0.f, 0.f);
    st.cur = -1; st.rcnt = 0; st.rmax = -INFINITY; st.qcur = 0.f;

    int e = lo + w;
    // x4 unroll: all loads unconditional and front-batched (8 LDG.128 in flight)
    for (; e + 24 < hi; e += 32) {
        int e1 = e + 8, e2 = e + 16, e3 = e + 24;
        int g0 = __ldg(batch + e);
        int g1 = __ldg(batch + e1);
        int g2 = __ldg(batch + e2);
        int g3 = __ldg(batch + e3);
        int s0 = __ldg(sel + e);
        int s1 = __ldg(sel + e1);
        int s2 = __ldg(sel + e2);
        int s3 = __ldg(sel + e3);
        const float4* r0 = (const float4*)(x + (size_t)e  * H);
        const float4* r1 = (const float4*)(x + (size_t)e1 * H);
        const float4* r2 = (const float4*)(x + (size_t)e2 * H);
        const float4* r3 = (const float4*)(x + (size_t)e3 * H);
        float4 xa0 = __ldg(r0 + l), xa1 = __ldg(r0 + 32 + l);
        float4 xb0 = __ldg(r1 + l), xb1 = __ldg(r1 + 32 + l);
        float4 xc0 = __ldg(r2 + l), xc1 = __ldg(r2 + 32 + l);
        float4 xd0 = __ldg(r3 + l), xd1 = __ldg(r3 + 32 + l);
        process_edge(st, g0, s0, xa0, xa1, wa0, wa1, e,  l);
        process_edge(st, g1, s1, xb0, xb1, wa0, wa1, e1, l);
        process_edge(st, g2, s2, xc0, xc1, wa0, wa1, e2, l);
        process_edge(st, g3, s3, xd0, xd1, wa0, wa1, e3, l);
    }
    for (; e < hi; e += 8) {
        int g = __ldg(batch + e);
        int s = __ldg(sel + e);
        const float4* row = (const float4*)(x + (size_t)e * H);
        float4 x0 = __ldg(row + l);
        float4 x1 = __ldg(row + 32 + l);
        process_edge(st, g, s, x0, x1, wa0, wa1, e, l);
    }
    flush_run(st, l);
}

// ---------------- fused post: softmax (blocks [0,G)) + full stop head -----
__device__ __forceinline__ void block_sum4(float v[STOPG], float4* red4, float out[STOPG]) {
    int l = threadIdx.x & 31, w = threadIdx.x >> 5;
    #pragma unroll
    for (int sh = 16; sh; sh >>= 1) {
        #pragma unroll
        for (int gg = 0; gg < STOPG; gg++)
            v[gg] += __shfl_xor_sync(0xFFFFFFFFu, v[gg], sh);
    }
    if (l == 0) red4[w] = make_float4(v[0], v[1], v[2], v[3]);
    __syncthreads();
    if (w == 0) {
        float4 xv = (l < 8) ? red4[l] : make_float4(0.f, 0.f, 0.f, 0.f);
        #pragma unroll
        for (int sh = 4; sh; sh >>= 1) {
            xv.x += __shfl_xor_sync(0xFFFFFFFFu, xv.x, sh);
            xv.y += __shfl_xor_sync(0xFFFFFFFFu, xv.y, sh);
            xv.z += __shfl_xor_sync(0xFFFFFFFFu, xv.z, sh);
            xv.w += __shfl_xor_sync(0xFFFFFFFFu, xv.w, sh);
        }
        if (l == 0) red4[0] = xv;
    }
    __syncthreads();
    float4 r = red4[0];
    out[0] = r.x; out[1] = r.y; out[2] = r.z; out[3] = r.w;
    __syncthreads();
}

__device__ __forceinline__ float dot4(float4 a, float4 b) {
    return a.x * b.x + a.y * b.y + a.z * b.z + a.w * b.w;
}

__global__ void __launch_bounds__(256) post_k(
        const int* __restrict__ sel,
        const float* __restrict__ qtok,
        const float* __restrict__ ln_g, const float* __restrict__ ln_b,
        const float* __restrict__ b1, const float* __restrict__ W2,
        const float* __restrict__ b2,
        float* __restrict__ out_edge, float* __restrict__ out_stop,
        float* __restrict__ out_pooled, int E, int G) {
    int t = threadIdx.x;
    int l = t & 31, w = t >> 5;

    if (blockIdx.x < (unsigned)G) {
        // -------- segment softmax + edge logits (precomputed bounds) ------
        __shared__ float red[32];
        __shared__ float s_lsum;
        int g = blockIdx.x;
        int lo = __ldg(g_seg + g);
        int hi = __ldg(g_seg + g + 1);
        if (lo >= hi) return;

        float m = fdec(g_z.maxenc[g]);
        float s = 0.f;
        for (int e = lo + t; e < hi; e += 256)
            if (__ldg(sel + e) == 0) s += __expf(__ldg(g_att + e) - m);
        #pragma unroll
        for (int sh = 16; sh; sh >>= 1) s += __shfl_xor_sync(0xFFFFFFFFu, s, sh);
        if (l == 0) red[w] = s;
        __syncthreads();
        if (w == 0) {
            float v = (l < 8) ? red[l] : 0.f;
            #pragma unroll
            for (int sh = 4; sh; sh >>= 1) v += __shfl_xor_sync(0xFFFFFFFFu, v, sh);
            if (l == 0) s_lsum = __logf(fmaxf(v, F32_EPS));
        }
        __syncthreads();
        float lsum = s_lsum;
        // log(max(p,eps)) = max(log p, log eps); log p = (att-m) - lsum
        for (int e = lo + t; e < hi; e += 256) {
            float o = LOG_EPS;
            if (__ldg(sel + e) == 0)
                o = fmaxf(__ldg(g_att + e) - m - lsum, LOG_EPS);
            out_edge[e] = o;
        }
    } else {
        // ---- stop head: thread t owns row t; coalesced interleaved weights
        __shared__ __align__(16) float ssh[STOPG][H];       // S/denom
        __shared__ __align__(16) float xsh[STOPG][2 * H];   // layernormed inputs
        __shared__ float4 red4[32];
        int g0 = (blockIdx.x - G) * STOPG;

        #pragma unroll
        for (int gg = 0; gg < STOPG; gg++) {
            int g = g0 + gg;
            float v = 0.f;
            if (g < G) {
                float denom = fmaxf((float)g_z.cnt[g], 1.0f);
                v = g_z.S[g * H + t] / denom;
            }
            ssh[gg][t] = v;
        }
        __syncthreads();

        // matvec1: pooled[t] = sum_c S[c] * W_edge[t][c]
        // WeI load: thread t -> address j*256+t: coalesced float4, independent per j
        float acc[STOPG];
        #pragma unroll
        for (int gg = 0; gg < STOPG; gg++) acc[gg] = 0.f;
        for (int j = 0; j < H / 4; j += 4) {
            float4 w0 = g_WeI[(j + 0) * H + t];
            float4 w1 = g_WeI[(j + 1) * H + t];
            float4 w2 = g_WeI[(j + 2) * H + t];
            float4 w3 = g_WeI[(j + 3) * H + t];
            #pragma unroll
            for (int gg = 0; gg < STOPG; gg++) {
                const float4* s4 = (const float4*)ssh[gg];
                acc[gg] += dot4(w0, s4[j]) + dot4(w1, s4[j + 1])
                         + dot4(w2, s4[j + 2]) + dot4(w3, s4[j + 3]);
            }
        }

        float pe[STOPG], qv[STOPG];
        #pragma unroll
        for (int gg = 0; gg < STOPG; gg++) {
            int g = g0 + gg;
            pe[gg] = acc[gg];
            qv[gg] = (g < G) ? qtok[(size_t)g * H + t] : 0.f;
            if (g < G) out_pooled[(size_t)g * H + t] = pe[gg];
        }

        // LayerNorm over 512 per graph
        float v[STOPG], mu[STOPG], var[STOPG];
        #pragma unroll
        for (int gg = 0; gg < STOPG; gg++) v[gg] = pe[gg] + qv[gg];
        block_sum4(v, red4, mu);
        float d0[STOPG], d1[STOPG];
        #pragma unroll
        for (int gg = 0; gg < STOPG; gg++) {
            mu[gg] *= (1.0f / (2 * H));
            d0[gg] = pe[gg] - mu[gg];
            d1[gg] = qv[gg] - mu[gg];
            v[gg] = d0[gg] * d0[gg] + d1[gg] * d1[gg];
        }
        block_sum4(v, red4, var);
        float lg0 = ln_g[t], lb0 = ln_b[t], lg1 = ln_g[H + t], lb1 = ln_b[H + t];
        #pragma unroll
        for (int gg = 0; gg < STOPG; gg++) {
            float rstd = rsqrtf(var[gg] * (1.0f / (2 * H)) + LN_EPS);
            xsh[gg][t]     = d0[gg] * rstd * lg0 + lb0;
            xsh[gg][H + t] = d1[gg] * rstd * lg1 + lb1;
        }
        __syncthreads();

        // matvec2: a1[t] = sum_c xn[c] * W1[t][c] (coalesced via W1I)
        #pragma unroll
        for (int gg = 0; gg < STOPG; gg++) acc[gg] = 0.f;
        for (int j = 0; j < 2 * H / 4; j += 4) {
            float4 w0 = g_W1I[(j + 0) * H + t];
            float4 w1 = g_W1I[(j + 1) * H + t];
            float4 w2 = g_W1I[(j + 2) * H + t];
            float4 w3 = g_W1I[(j + 3) * H + t];
            #pragma unroll
            for (int gg = 0; gg < STOPG; gg++) {
                const float4* x4 = (const float4*)xsh[gg];
                acc[gg] += dot4(w0, x4[j]) + dot4(w1, x4[j + 1])
                         + dot4(w2, x4[j + 2]) + dot4(w3, x4[j + 3]);
            }
        }

        float bb = __ldg(b1 + t), wv2 = __ldg(W2 + t);
        #pragma unroll
        for (int gg = 0; gg < STOPG; gg++) {
            float a1 = acc[gg] + bb;
            float h1 = 0.5f * a1 * (1.0f + erff(a1 * 0.70710678118654752f));
            v[gg] = h1 * wv2;
        }
        float tot[STOPG];
        block_sum4(v, red4, tot);
        if (t == 0) {
            float bias = b2[0];
            #pragma unroll
            for (int gg = 0; gg < STOPG; gg++)
                if (g0 + gg < G) out_stop[g0 + gg] = tot[gg] + bias;
        }
    }
}

// ---------------- launch ----------------
extern "C" void kernel_launch(void* const* d_in, const int* in_sizes, int n_in,
                              void* d_out, int out_size) {
    const float* edge_tokens = (const float*)d_in[0];
    const float* qtok        = (const float*)d_in[1];
    const int*   batch       = (const int*)d_in[2];
    const int*   sel         = (const int*)d_in[3];
    const float* W_edge      = (const float*)d_in[4];
    const float* W_query     = (const float*)d_in[5];
    const float* att_vec     = (const float*)d_in[6];
    const float* ln_g        = (const float*)d_in[7];
    const float* ln_b        = (const float*)d_in[8];
    const float* W1          = (const float*)d_in[9];
    const float* b1          = (const float*)d_in[10];
    const float* W2          = (const float*)d_in[11];
    const float* b2          = (const float*)d_in[12];

    int E = in_sizes[0] / H;
    int G = in_sizes[1] / H;

    float* out = (float*)d_out;
    float* out_edge   = out;            // [E]
    float* out_stop   = out + E;        // [G]
    float* out_pooled = out + E + G;    // [G*H]

    void* zp = nullptr;
    cudaGetSymbolAddress(&zp, g_z);
    cudaMemsetAsync(zp, 0, sizeof(Scratch));

    int nstop = (G + STOPG - 1) / STOPG;
    prew_k<<<226, 256>>>(W_edge, W_query, W1, att_vec, batch, E, G);
    qatt_k<<<(G + 7) / 8, 256>>>(qtok, G);
    pass1_k<<<NBLK_P1, 256>>>(edge_tokens, batch, sel, E);
    post_k<<<G + nstop, 256>>>(sel, qtok, ln_g, ln_b, b1, W2, b2,
                               out_edge, out_stop, out_pooled, E, G);
}

// round 14
// speedup vs baseline: 1.5578x; 1.0944x over previous
#include <cuda_runtime.h>
#include <math.h>

#define H 256
#define MAXE 500000
#define MAXG 256
#define FRONTIER_BONUS 0.5f
#define LN_EPS 1e-5f
#define F32_EPS 1.1920929e-07f
#define LOG_EPS -15.942385152878742f   // ln(2^-23)
#define NBLK_P1 1184
#define STOPG 4

// ---------------- device scratch (single memset-able struct) ----------------
// __align__(16) REQUIRED: float4 (LDG.128) access to w_att and S.
struct __align__(16) Scratch {
    float    S[MAXG * H];     // segment sums of edge_tokens
    float    w_att[H];        // att_vec @ W_edge  (atomic partials)
    float    w_q[H];          // att_vec @ W_query (atomic partials)
};
__device__ Scratch g_z;
__device__ float g_qatt[MAXG];       // fully overwritten each run
__device__ float g_att[MAXE];        // raw dot d per edge (overwritten)
__device__ int   g_seg[MAXG + 1];    // segment bounds (fully overwritten)
// Interleaved weights: WI4[c/4 * 256 + r] = {W[r][c..c+3]}
// -> thread t reading row t's j-th quad hits address (j*256+t): coalesced.
__device__ float4 g_WeI[(H / 4) * H];          // W_edge interleaved  (64*256)
__device__ float4 g_W1I[(2 * H / 4) * H];      // W1 interleaved      (128*256)

// --- setup: w_att/w_q partials (0-31) + weight interleave (32-223) + seg ---
__global__ void __launch_bounds__(256) prew_k(const float* __restrict__ W_edge,
                       const float* __restrict__ W_query,
                       const float* __restrict__ W1,
                       const float* __restrict__ att_vec,
                       const int* __restrict__ batch, int E, int G) {
    __shared__ float sh[32][33];
    int b = blockIdx.x, t = threadIdx.x;
    if (b < 32) {
        int m = b >> 4;                   // 0: W_edge, 1: W_query
        int c = b & 15;                   // row chunk of 16
        const float* W = m ? W_query : W_edge;
        int i0 = c * 16;
        float s = 0.f;
        #pragma unroll
        for (int i = 0; i < 16; i++)
            s = fmaf(__ldg(att_vec + i0 + i), __ldg(W + (i0 + i) * H + t), s);
        atomicAdd((m ? g_z.w_q : g_z.w_att) + t, s);
    } else if (b < 96) {
        // interleave W_edge [256 x 256]: 8x8 tiles of 32x32
        int bt = b - 32;
        int ti = bt >> 3, tj = bt & 7;    // row tile, col tile
        int x = t & 31, y = t >> 5;       // 32 x 8
        #pragma unroll
        for (int k = 0; k < 4; k++)
            sh[y + 8 * k][x] = __ldg(W_edge + (ti * 32 + y + 8 * k) * H + tj * 32 + x);
        __syncthreads();
        int rl = t & 31, jl = t >> 5;     // local row, local col-quad
        float4 v = make_float4(sh[rl][jl * 4 + 0], sh[rl][jl * 4 + 1],
                               sh[rl][jl * 4 + 2], sh[rl][jl * 4 + 3]);
        g_WeI[(tj * 8 + jl) * H + ti * 32 + rl] = v;
    } else if (b < 224) {
        // interleave W1 [256 x 512]: 8x16 = 128 tiles of 32x32
        int bt = b - 96;
        int ti = bt >> 4, tj = bt & 15;
        int x = t & 31, y = t >> 5;
        #pragma unroll
        for (int k = 0; k < 4; k++)
            sh[y + 8 * k][x] = __ldg(W1 + (ti * 32 + y + 8 * k) * (2 * H) + tj * 32 + x);
        __syncthreads();
        int rl = t & 31, jl = t >> 5;
        float4 v = make_float4(sh[rl][jl * 4 + 0], sh[rl][jl * 4 + 1],
                               sh[rl][jl * 4 + 2], sh[rl][jl * 4 + 3]);
        g_W1I[(tj * 8 + jl) * H + ti * 32 + rl] = v;
    } else {
        // segment bounds: g_seg[i] = lower_bound(batch, i)
        int i = (b - 224) * 256 + t;
        if (i > G) return;
        int lo = 0, hi = E;
        while (lo < hi) {
            int mid = (lo + hi) >> 1;
            if (__ldg(batch + mid) < i) lo = mid + 1; else hi = mid;
        }
        g_seg[i] = lo;
    }
}

// ---------------- qatt[g] = question_tokens[g] . w_q ----------------
__global__ void __launch_bounds__(256) qatt_k(const float* __restrict__ qtok, int G) {
    int w = threadIdx.x >> 5, l = threadIdx.x & 31;
    int g = blockIdx.x * 8 + w;
    if (g >= G) return;
    float s = 0.f;
    #pragma unroll
    for (int k = 0; k < 8; k++) {
        int j = l + 32 * k;
        s = fmaf(qtok[(size_t)g * H + j], g_z.w_q[j], s);
    }
    #pragma unroll
    for (int sh = 16; sh; sh >>= 1) s += __shfl_xor_sync(0xFFFFFFFFu, s, sh);
    if (l == 0) g_qatt[g] = s;
}

// --------- main streaming pass: warp-per-edge, x4 unroll, LEAN body -------
// Only: segment-sum accumulation + raw dot d stored. Activation/max/softmax
// all deferred to post (which sweeps g_att anyway).
struct RunState {
    float4 a0, a1;
    int cur;
};

__device__ __forceinline__ void flush_run(RunState& st, int l) {
    if (st.cur < 0) return;
    float* Sp = &g_z.S[st.cur * H];
    atomicAdd(Sp + 4 * l + 0, st.a0.x);
    atomicAdd(Sp + 4 * l + 1, st.a0.y);
    atomicAdd(Sp + 4 * l + 2, st.a0.z);
    atomicAdd(Sp + 4 * l + 3, st.a0.w);
    atomicAdd(Sp + 128 + 4 * l + 0, st.a1.x);
    atomicAdd(Sp + 128 + 4 * l + 1, st.a1.y);
    atomicAdd(Sp + 128 + 4 * l + 2, st.a1.z);
    atomicAdd(Sp + 128 + 4 * l + 3, st.a1.w);
}

__device__ __forceinline__ void process_edge(RunState& st, int g,
                                             float4 x0, float4 x1,
                                             float4 wa0, float4 wa1,
                                             int e, int l) {
    if (g != st.cur) {
        flush_run(st, l);
        st.a0 = make_float4(0.f, 0.f, 0.f, 0.f);
        st.a1 = make_float4(0.f, 0.f, 0.f, 0.f);
        st.cur = g;
    }
    st.a0.x += x0.x; st.a0.y += x0.y; st.a0.z += x0.z; st.a0.w += x0.w;
    st.a1.x += x1.x; st.a1.y += x1.y; st.a1.z += x1.z; st.a1.w += x1.w;
    float d = x0.x * wa0.x + x0.y * wa0.y + x0.z * wa0.z + x0.w * wa0.w
            + x1.x * wa1.x + x1.y * wa1.y + x1.z * wa1.z + x1.w * wa1.w;
    #pragma unroll
    for (int sh = 16; sh; sh >>= 1) d += __shfl_xor_sync(0xFFFFFFFFu, d, sh);
    if (l == 0) g_att[e] = d;
}

__global__ void __launch_bounds__(256) pass1_k(const float* __restrict__ x,
                        const int* __restrict__ batch,
                        int E) {
    int chunk = (E + NBLK_P1 - 1) / NBLK_P1;
    int lo = blockIdx.x * chunk;
    int hi = min(E, lo + chunk);
    int w = threadIdx.x >> 5, l = threadIdx.x & 31;

    const float4* wav = (const float4*)g_z.w_att;
    float4 wa0 = wav[l];
    float4 wa1 = wav[32 + l];

    RunState st;
    st.a0 = make_float4(0.f, 0.f, 0.f, 0.f);
    st.a1 = make_float4(0.f, 0.f, 0.f, 0.f);
    st.cur = -1;

    int e = lo + w;
    // x4 unroll: all loads unconditional and front-batched (8 LDG.128 in flight)
    for (; e + 24 < hi; e += 32) {
        int e1 = e + 8, e2 = e + 16, e3 = e + 24;
        int g0 = __ldg(batch + e);
        int g1 = __ldg(batch + e1);
        int g2 = __ldg(batch + e2);
        int g3 = __ldg(batch + e3);
        const float4* r0 = (const float4*)(x + (size_t)e  * H);
        const float4* r1 = (const float4*)(x + (size_t)e1 * H);
        const float4* r2 = (const float4*)(x + (size_t)e2 * H);
        const float4* r3 = (const float4*)(x + (size_t)e3 * H);
        float4 xa0 = __ldg(r0 + l), xa1 = __ldg(r0 + 32 + l);
        float4 xb0 = __ldg(r1 + l), xb1 = __ldg(r1 + 32 + l);
        float4 xc0 = __ldg(r2 + l), xc1 = __ldg(r2 + 32 + l);
        float4 xd0 = __ldg(r3 + l), xd1 = __ldg(r3 + 32 + l);
        process_edge(st, g0, xa0, xa1, wa0, wa1, e,  l);
        process_edge(st, g1, xb0, xb1, wa0, wa1, e1, l);
        process_edge(st, g2, xc0, xc1, wa0, wa1, e2, l);
        process_edge(st, g3, xd0, xd1, wa0, wa1, e3, l);
    }
    for (; e < hi; e += 8) {
        int g = __ldg(batch + e);
        const float4* row = (const float4*)(x + (size_t)e * H);
        float4 x0 = __ldg(row + l);
        float4 x1 = __ldg(row + 32 + l);
        process_edge(st, g, x0, x1, wa0, wa1, e, l);
    }
    flush_run(st, l);
}

// ---------------- fused post: softmax (blocks [0,G)) + full stop head -----
__device__ __forceinline__ void block_sum4(float v[STOPG], float4* red4, float out[STOPG]) {
    int l = threadIdx.x & 31, w = threadIdx.x >> 5;
    #pragma unroll
    for (int sh = 16; sh; sh >>= 1) {
        #pragma unroll
        for (int gg = 0; gg < STOPG; gg++)
            v[gg] += __shfl_xor_sync(0xFFFFFFFFu, v[gg], sh);
    }
    if (l == 0) red4[w] = make_float4(v[0], v[1], v[2], v[3]);
    __syncthreads();
    if (w == 0) {
        float4 xv = (l < 8) ? red4[l] : make_float4(0.f, 0.f, 0.f, 0.f);
        #pragma unroll
        for (int sh = 4; sh; sh >>= 1) {
            xv.x += __shfl_xor_sync(0xFFFFFFFFu, xv.x, sh);
            xv.y += __shfl_xor_sync(0xFFFFFFFFu, xv.y, sh);
            xv.z += __shfl_xor_sync(0xFFFFFFFFu, xv.z, sh);
            xv.w += __shfl_xor_sync(0xFFFFFFFFu, xv.w, sh);
        }
        if (l == 0) red4[0] = xv;
    }
    __syncthreads();
    float4 r = red4[0];
    out[0] = r.x; out[1] = r.y; out[2] = r.z; out[3] = r.w;
    __syncthreads();
}

__device__ __forceinline__ float dot4(float4 a, float4 b) {
    return a.x * b.x + a.y * b.y + a.z * b.z + a.w * b.w;
}

// r = LeakyReLU(d + qatt) + bonus * (sel == 0)
__device__ __forceinline__ float edge_r(float d, float qa, int selv) {
    float r = d + qa;
    r = r > 0.f ? r : 0.2f * r;
    if (selv == 0) r += FRONTIER_BONUS;
    return r;
}

__global__ void __launch_bounds__(256) post_k(
        const int* __restrict__ sel,
        const float* __restrict__ qtok,
        const float* __restrict__ ln_g, const float* __restrict__ ln_b,
        const float* __restrict__ b1, const float* __restrict__ W2,
        const float* __restrict__ b2,
        float* __restrict__ out_edge, float* __restrict__ out_stop,
        float* __restrict__ out_pooled, int E, int G) {
    int t = threadIdx.x;
    int l = t & 31, w = t >> 5;

    if (blockIdx.x < (unsigned)G) {
        // ------ segment softmax: 3 passes (max, sum, write) over L2-hot data
        __shared__ float red[32];
        __shared__ float s_m, s_lsum;
        int g = blockIdx.x;
        int lo = __ldg(g_seg + g);
        int hi = __ldg(g_seg + g + 1);
        if (lo >= hi) return;
        float qa = g_qatt[g];

        // pass A: segment max of r (over ALL edges, matching reference)
        float mx = -INFINITY;
        for (int e = lo + t; e < hi; e += 256)
            mx = fmaxf(mx, edge_r(__ldg(g_att + e), qa, __ldg(sel + e)));
        #pragma unroll
        for (int sh = 16; sh; sh >>= 1)
            mx = fmaxf(mx, __shfl_xor_sync(0xFFFFFFFFu, mx, sh));
        if (l == 0) red[w] = mx;
        __syncthreads();
        if (w == 0) {
            float v = (l < 8) ? red[l] : -INFINITY;
            #pragma unroll
            for (int sh = 4; sh; sh >>= 1)
                v = fmaxf(v, __shfl_xor_sync(0xFFFFFFFFu, v, sh));
            if (l == 0) s_m = v;
        }
        __syncthreads();
        float m = s_m;

        // pass B: sum of exp over candidates
        float s = 0.f;
        for (int e = lo + t; e < hi; e += 256) {
            int sv = __ldg(sel + e);
            if (sv == 0) s += __expf(edge_r(__ldg(g_att + e), qa, sv) - m);
        }
        #pragma unroll
        for (int sh = 16; sh; sh >>= 1) s += __shfl_xor_sync(0xFFFFFFFFu, s, sh);
        if (l == 0) red[w] = s;
        __syncthreads();
        if (w == 0) {
            float v = (l < 8) ? red[l] : 0.f;
            #pragma unroll
            for (int sh = 4; sh; sh >>= 1) v += __shfl_xor_sync(0xFFFFFFFFu, v, sh);
            if (l == 0) s_lsum = __logf(fmaxf(v, F32_EPS));
        }
        __syncthreads();
        float lsum = s_lsum;

        // pass C: write logits. log(max(p,eps)) = max((r-m)-lsum, log eps)
        for (int e = lo + t; e < hi; e += 256) {
            int sv = __ldg(sel + e);
            float o = LOG_EPS;
            if (sv == 0)
                o = fmaxf(edge_r(__ldg(g_att + e), qa, sv) - m - lsum, LOG_EPS);
            out_edge[e] = o;
        }
    } else {
        // ---- stop head: thread t owns row t; interleaved weights, j-step 8
        __shared__ __align__(16) float ssh[STOPG][H];       // S/denom
        __shared__ __align__(16) float xsh[STOPG][2 * H];   // layernormed inputs
        __shared__ float4 red4[32];
        int g0 = (blockIdx.x - G) * STOPG;

        #pragma unroll
        for (int gg = 0; gg < STOPG; gg++) {
            int g = g0 + gg;
            float v = 0.f;
            if (g < G) {
                int c = __ldg(g_seg + g + 1) - __ldg(g_seg + g);
                v = g_z.S[g * H + t] / fmaxf((float)c, 1.0f);
            }
            ssh[gg][t] = v;
        }
        __syncthreads();

        // matvec1: pooled[t] = sum_c S[c] * W_edge[t][c]; 8 loads in flight
        float acc[STOPG];
        #pragma unroll
        for (int gg = 0; gg < STOPG; gg++) acc[gg] = 0.f;
        for (int j = 0; j < H / 4; j += 8) {
            float4 wv[8];
            #pragma unroll
            for (int k = 0; k < 8; k++) wv[k] = g_WeI[(j + k) * H + t];
            #pragma unroll
            for (int gg = 0; gg < STOPG; gg++) {
                const float4* s4 = (const float4*)ssh[gg];
                float a = 0.f;
                #pragma unroll
                for (int k = 0; k < 8; k++) a += dot4(wv[k], s4[j + k]);
                acc[gg] += a;
            }
        }

        float pe[STOPG], qv[STOPG];
        #pragma unroll
        for (int gg = 0; gg < STOPG; gg++) {
            int g = g0 + gg;
            pe[gg] = acc[gg];
            qv[gg] = (g < G) ? qtok[(size_t)g * H + t] : 0.f;
            if (g < G) out_pooled[(size_t)g * H + t] = pe[gg];
        }

        // LayerNorm over 512 per graph
        float v[STOPG], mu[STOPG], var[STOPG];
        #pragma unroll
        for (int gg = 0; gg < STOPG; gg++) v[gg] = pe[gg] + qv[gg];
        block_sum4(v, red4, mu);
        float d0[STOPG], d1[STOPG];
        #pragma unroll
        for (int gg = 0; gg < STOPG; gg++) {
            mu[gg] *= (1.0f / (2 * H));
            d0[gg] = pe[gg] - mu[gg];
            d1[gg] = qv[gg] - mu[gg];
            v[gg] = d0[gg] * d0[gg] + d1[gg] * d1[gg];
        }
        block_sum4(v, red4, var);
        float lg0 = ln_g[t], lb0 = ln_b[t], lg1 = ln_g[H + t], lb1 = ln_b[H + t];
        #pragma unroll
        for (int gg = 0; gg < STOPG; gg++) {
            float rstd = rsqrtf(var[gg] * (1.0f / (2 * H)) + LN_EPS);
            xsh[gg][t]     = d0[gg] * rstd * lg0 + lb0;
            xsh[gg][H + t] = d1[gg] * rstd * lg1 + lb1;
        }
        __syncthreads();

        // matvec2: a1[t] = sum_c xn[c] * W1[t][c]; 8 loads in flight
        #pragma unroll
        for (int gg = 0; gg < STOPG; gg++) acc[gg] = 0.f;
        for (int j = 0; j < 2 * H / 4; j += 8) {
            float4 wv[8];
            #pragma unroll
            for (int k = 0; k < 8; k++) wv[k] = g_W1I[(j + k) * H + t];
            #pragma unroll
            for (int gg = 0; gg < STOPG; gg++) {
                const float4* x4 = (const float4*)xsh[gg];
                float a = 0.f;
                #pragma unroll
                for (int k = 0; k < 8; k++) a += dot4(wv[k], x4[j + k]);
                acc[gg] += a;
            }
        }

        float bb = __ldg(b1 + t), wv2 = __ldg(W2 + t);
        #pragma unroll
        for (int gg = 0; gg < STOPG; gg++) {
            float a1 = acc[gg] + bb;
            float h1 = 0.5f * a1 * (1.0f + erff(a1 * 0.70710678118654752f));
            v[gg] = h1 * wv2;
        }
        float tot[STOPG];
        block_sum4(v, red4, tot);
        if (t == 0) {
            float bias = b2[0];
            #pragma unroll
            for (int gg = 0; gg < STOPG; gg++)
                if (g0 + gg < G) out_stop[g0 + gg] = tot[gg] + bias;
        }
    }
}

// ---------------- launch ----------------
extern "C" void kernel_launch(void* const* d_in, const int* in_sizes, int n_in,
                              void* d_out, int out_size) {
    const float* edge_tokens = (const float*)d_in[0];
    const float* qtok        = (const float*)d_in[1];
    const int*   batch       = (const int*)d_in[2];
    const int*   sel         = (const int*)d_in[3];
    const float* W_edge      = (const float*)d_in[4];
    const float* W_query     = (const float*)d_in[5];
    const float* att_vec     = (const float*)d_in[6];
    const float* ln_g        = (const float*)d_in[7];
    const float* ln_b        = (const float*)d_in[8];
    const float* W1          = (const float*)d_in[9];
    const float* b1          = (const float*)d_in[10];
    const float* W2          = (const float*)d_in[11];
    const float* b2          = (const float*)d_in[12];

    int E = in_sizes[0] / H;
    int G = in_sizes[1] / H;

    float* out = (float*)d_out;
    float* out_edge   = out;            // [E]
    float* out_stop   = out + E;        // [G]
    float* out_pooled = out + E + G;    // [G*H]

    void* zp = nullptr;
    cudaGetSymbolAddress(&zp, g_z);
    cudaMemsetAsync(zp, 0, sizeof(Scratch));

    int nstop = (G + STOPG - 1) / STOPG;
    prew_k<<<226, 256>>>(W_edge, W_query, W1, att_vec, batch, E, G);
    qatt_k<<<(G + 7) / 8, 256>>>(qtok, G);
    pass1_k<<<NBLK_P1, 256>>>(edge_tokens, batch, E);
    post_k<<<G + nstop, 256>>>(sel, qtok, ln_g, ln_b, b1, W2, b2,
                               out_edge, out_stop, out_pooled, E, G);
}